// round 2
// baseline (speedup 1.0000x reference)
#include <cuda_runtime.h>
#include <cuda_bf16.h>
#include <cstdint>

// Problem constants
#define BS_     4096
#define IN_DIM_ 2048
#define NN_     16384
#define DTOT_   129      // 2*K+1 + SLACK = 65 + 64
#define KPAD_   144      // padded K for the big GEMM (multiple of 16)
#define INV_SQRT_N_ 0.0078125f          // 1/128 exact
#define SQRT2_      1.41421356237309515f

// Scratch (allocation-free rule: __device__ globals)
__device__ float g_buf[BS_ * KPAD_];          // [4096][144] coefficients
__device__ float M_buf[KPAD_ * NN_];          // [144][16384] basis (ones/cos/sin/Ws^T, zero pad)

// ---------------------------------------------------------------------------
// Kernel 1: g = scale( x @ W_proj^T + b_proj ), zero-padded to KPAD_
// Tiles: BM1=64 (batch) x BN1=32 (d) x BK1=32, 256 threads, 4x2 micro-tile
// ---------------------------------------------------------------------------
#define BM1 64
#define BN1 32
#define BK1 32

__global__ __launch_bounds__(256) void proj_kernel(
    const float* __restrict__ x,
    const float* __restrict__ Wp,
    const float* __restrict__ bp)
{
    __shared__ float Xs[BK1][BM1 + 1];   // [k][b]
    __shared__ float Wsm[BK1][BN1 + 1];  // [k][d]

    const int tid = threadIdx.x;
    const int bm = blockIdx.y * BM1;
    const int bn = blockIdx.x * BN1;
    const int tx = tid & 15;     // d  (x2)
    const int ty = tid >> 4;     // b  (x4)

    float acc[4][2] = {};

    for (int kk = 0; kk < IN_DIM_; kk += BK1) {
        // load X tile: 64 rows x 32 k  (512 float4, 2 per thread)
        #pragma unroll
        for (int r = 0; r < 2; r++) {
            int id = tid + r * 256;
            int row = id >> 3;          // 0..63
            int c4  = id & 7;           // 0..7
            float4 v = *(const float4*)(x + (size_t)(bm + row) * IN_DIM_ + kk + c4 * 4);
            Xs[c4 * 4 + 0][row] = v.x;
            Xs[c4 * 4 + 1][row] = v.y;
            Xs[c4 * 4 + 2][row] = v.z;
            Xs[c4 * 4 + 3][row] = v.w;
        }
        // load W tile: 32 d-rows x 32 k (256 float4, 1 per thread), guard d<129
        {
            int row = tid >> 3;         // 0..31
            int c4  = tid & 7;
            int d   = bn + row;
            float4 v = make_float4(0.f, 0.f, 0.f, 0.f);
            if (d < DTOT_)
                v = *(const float4*)(Wp + (size_t)d * IN_DIM_ + kk + c4 * 4);
            Wsm[c4 * 4 + 0][row] = v.x;
            Wsm[c4 * 4 + 1][row] = v.y;
            Wsm[c4 * 4 + 2][row] = v.z;
            Wsm[c4 * 4 + 3][row] = v.w;
        }
        __syncthreads();

        #pragma unroll
        for (int k = 0; k < BK1; k++) {
            float b0 = Wsm[k][tx * 2 + 0];
            float b1 = Wsm[k][tx * 2 + 1];
            #pragma unroll
            for (int i = 0; i < 4; i++) {
                float a = Xs[k][ty * 4 + i];
                acc[i][0] += a * b0;
                acc[i][1] += a * b1;
            }
        }
        __syncthreads();
    }

    // Epilogue: add bias, fold 1/sqrt(N) and sqrt(2) scales, zero pad
    #pragma unroll
    for (int i = 0; i < 4; i++) {
        int b = bm + ty * 4 + i;
        #pragma unroll
        for (int j = 0; j < 2; j++) {
            int d = bn + tx * 2 + j;
            if (d < KPAD_) {
                float v = 0.f;
                if (d < DTOT_) {
                    v = acc[i][j] + bp[d];
                    if (d == 0)        v *= INV_SQRT_N_;
                    else if (d <= 64)  v *= INV_SQRT_N_ * SQRT2_;
                    // d in [65,128]: slack, scale 1
                }
                g_buf[(size_t)b * KPAD_ + d] = v;
            }
        }
    }
}

// ---------------------------------------------------------------------------
// Kernel 2: build M basis.
//   row 0        : 1
//   row 2k-1     : cos(2*pi*k*n/N)   k=1..32   (exact arg via (k*n)&(N-1))
//   row 2k       : sin(2*pi*k*n/N)
//   row 65+j     : Ws[n][j]          j=0..63   (transposed slack weights)
//   rows 129..143: 0
// ---------------------------------------------------------------------------
__global__ __launch_bounds__(256) void build_M_kernel(const float* __restrict__ Ws)
{
    const int n = blockIdx.x * 256 + threadIdx.x;
    M_buf[n] = 1.0f;
    #pragma unroll
    for (int k = 1; k <= 32; k++) {
        int m = (k * n) & (NN_ - 1);
        float t = (float)(2 * m) * (1.0f / (float)NN_);  // exact: 2m/16384
        float s, c;
        sincospif(t, &s, &c);                            // sin/cos(2*pi*m/N)
        M_buf[(size_t)(2 * k - 1) * NN_ + n] = c;
        M_buf[(size_t)(2 * k)     * NN_ + n] = s;
    }
    #pragma unroll 8
    for (int j = 0; j < 64; j++)
        M_buf[(size_t)(65 + j) * NN_ + n] = Ws[(size_t)n * 64 + j];
    #pragma unroll
    for (int r = DTOT_; r < KPAD_; r++)
        M_buf[(size_t)r * NN_ + n] = 0.f;
}

// ---------------------------------------------------------------------------
// Kernel 3: out[4096][16384] = g[4096][144] @ M[144][16384]
// Classic fp32 tiled GEMM: BM=64, BN=64, BK=16, 256 threads, 4x4 micro-tile
// ---------------------------------------------------------------------------
#define BM3 64
#define BN3 64
#define BK3 16
#define AROW_ 68   // padded As row length (16B-aligned, reduces store conflicts)

__global__ __launch_bounds__(256) void out_gemm_kernel(float* __restrict__ C)
{
    __shared__ float As[BK3][AROW_];   // [k][b]
    __shared__ float Bs[BK3][BN3];     // [k][n]

    const int tid = threadIdx.x;
    const int bm = blockIdx.y * BM3;
    const int bn = blockIdx.x * BN3;
    const int tx = tid & 15;     // n (x4)
    const int ty = tid >> 4;     // b (x4)

    float acc[4][4] = {};

    for (int kk = 0; kk < KPAD_; kk += BK3) {
        // A tile: 64 b-rows x 16 k = 256 float4, one per thread (transposed store)
        {
            int row = tid >> 2;         // 0..63
            int c4  = tid & 3;          // 0..3
            float4 v = *(const float4*)(&g_buf[(size_t)(bm + row) * KPAD_ + kk + c4 * 4]);
            As[c4 * 4 + 0][row] = v.x;
            As[c4 * 4 + 1][row] = v.y;
            As[c4 * 4 + 2][row] = v.z;
            As[c4 * 4 + 3][row] = v.w;
        }
        // B tile: 16 k-rows x 64 n = 256 float4, one per thread (direct store)
        {
            int k  = tid >> 4;          // 0..15
            int c4 = tid & 15;          // 0..15
            float4 v = *(const float4*)(&M_buf[(size_t)(kk + k) * NN_ + bn + c4 * 4]);
            *(float4*)(&Bs[k][c4 * 4]) = v;
        }
        __syncthreads();

        #pragma unroll
        for (int k = 0; k < BK3; k++) {
            float4 av = *(const float4*)(&As[k][ty * 4]);
            float4 bv = *(const float4*)(&Bs[k][tx * 4]);
            float a[4] = {av.x, av.y, av.z, av.w};
            float b[4] = {bv.x, bv.y, bv.z, bv.w};
            #pragma unroll
            for (int i = 0; i < 4; i++)
                #pragma unroll
                for (int j = 0; j < 4; j++)
                    acc[i][j] += a[i] * b[j];
        }
        __syncthreads();
    }

    #pragma unroll
    for (int i = 0; i < 4; i++) {
        float4 v = make_float4(acc[i][0], acc[i][1], acc[i][2], acc[i][3]);
        *(float4*)(&C[(size_t)(bm + ty * 4 + i) * NN_ + bn + tx * 4]) = v;
    }
}

// ---------------------------------------------------------------------------
extern "C" void kernel_launch(void* const* d_in, const int* in_sizes, int n_in,
                              void* d_out, int out_size)
{
    const float* x  = (const float*)d_in[0];   // [4096, 2048]
    const float* Wp = (const float*)d_in[1];   // [129, 2048]
    const float* bp = (const float*)d_in[2];   // [129]
    const float* Ws = (const float*)d_in[3];   // [16384, 64]
    float* out = (float*)d_out;                // [4096, 16384]

    // g = scaled projection  (d tiles: ceil(144/32)=5)
    proj_kernel<<<dim3(5, BS_ / BM1), 256>>>(x, Wp, bp);
    // M = [ones; cos/sin basis; Ws^T; zero pad]
    build_M_kernel<<<NN_ / 256, 256>>>(Ws);
    // out = g @ M
    out_gemm_kernel<<<dim3(NN_ / BN3, BS_ / BM3), 256>>>(out);
}

// round 5
// speedup vs baseline: 2.3877x; 2.3877x over previous
#include <cuda_runtime.h>
#include <cuda_bf16.h>
#include <cstdint>

#define BS_     4096
#define IN_DIM_ 2048
#define NN_     16384
#define DTOT_   129
#define KD_     144          // logical K of the fused GEMM (129 padded to 144)
#define KP2     448          // tripled K (3*144=432) padded to 448
#define KSPLIT  8
#define INV_SQRT_N_ 0.0078125f
#define SQRT2_      1.41421356237309515f

__device__ float         P_buf[KSPLIT * BS_ * KD_];
__device__ __nv_bfloat16 A2[BS_ * KP2];     // [b][k']   = [Ah | Ah | Al | 0]
__device__ __nv_bfloat16 B2[NN_ * KP2];     // [n][k']   = [Bh | Bl | Bh | 0]

// ---------------- PTX helpers (plain sm_80+ features only) ----------------
__device__ __forceinline__ uint32_t s2u(const void* p) {
    uint32_t a; asm("{.reg .u64 t; cvta.to.shared.u64 t,%1; cvt.u32.u64 %0,t;}" : "=r"(a) : "l"(p));
    return a;
}
#define CP_ASYNC16(dst, src) asm volatile("cp.async.cg.shared.global [%0], [%1], 16;" :: "r"(dst), "l"(src))
#define CP_COMMIT()          asm volatile("cp.async.commit_group;" ::: "memory")
#define CP_WAIT(n)           asm volatile("cp.async.wait_group %0;" :: "n"(n) : "memory")
#define LDSM4(r, addr) asm volatile("ldmatrix.sync.aligned.m8n8.x4.shared.b16 {%0,%1,%2,%3}, [%4];" \
    : "=r"((r)[0]), "=r"((r)[1]), "=r"((r)[2]), "=r"((r)[3]) : "r"(addr))
#define MMA16816(d, a, b) asm volatile( \
    "mma.sync.aligned.m16n8k16.row.col.f32.bf16.bf16.f32 " \
    "{%0,%1,%2,%3}, {%4,%5,%6,%7}, {%8,%9}, {%0,%1,%2,%3};" \
    : "+f"((d)[0]), "+f"((d)[1]), "+f"((d)[2]), "+f"((d)[3]) \
    : "r"((a)[0]), "r"((a)[1]), "r"((a)[2]), "r"((a)[3]), "r"((b)[0]), "r"((b)[1]))

// ---------------- Kernel 1: proj partials (split-K over IN_DIM) ----------------
#define BM1 64
#define BN1 32
#define BK1 32
__global__ __launch_bounds__(256) void proj_kernel(const float* __restrict__ x,
                                                   const float* __restrict__ Wp)
{
    __shared__ float Xs[BK1][BM1 + 1];
    __shared__ float Wsm[BK1][BN1 + 1];
    const int tid = threadIdx.x;
    const int bm = blockIdx.y * BM1, bn = blockIdx.x * BN1;
    const int s = blockIdx.z;
    const int k0 = s * (IN_DIM_ / KSPLIT);
    const int tx = tid & 15, ty = tid >> 4;
    float acc[4][2] = {};

    for (int kk = k0; kk < k0 + IN_DIM_ / KSPLIT; kk += BK1) {
        #pragma unroll
        for (int r = 0; r < 2; r++) {
            int id = tid + r * 256, row = id >> 3, c4 = id & 7;
            float4 v = *(const float4*)(x + (size_t)(bm + row) * IN_DIM_ + kk + c4 * 4);
            Xs[c4*4+0][row]=v.x; Xs[c4*4+1][row]=v.y; Xs[c4*4+2][row]=v.z; Xs[c4*4+3][row]=v.w;
        }
        {
            int row = tid >> 3, c4 = tid & 7, d = bn + row;
            float4 v = make_float4(0.f,0.f,0.f,0.f);
            if (d < DTOT_) v = *(const float4*)(Wp + (size_t)d * IN_DIM_ + kk + c4 * 4);
            Wsm[c4*4+0][row]=v.x; Wsm[c4*4+1][row]=v.y; Wsm[c4*4+2][row]=v.z; Wsm[c4*4+3][row]=v.w;
        }
        __syncthreads();
        #pragma unroll
        for (int k = 0; k < BK1; k++) {
            float b0 = Wsm[k][tx*2+0], b1 = Wsm[k][tx*2+1];
            #pragma unroll
            for (int i = 0; i < 4; i++) {
                float a = Xs[k][ty*4+i];
                acc[i][0] += a * b0; acc[i][1] += a * b1;
            }
        }
        __syncthreads();
    }
    float* P = P_buf + (size_t)s * BS_ * KD_;
    #pragma unroll
    for (int i = 0; i < 4; i++)
        #pragma unroll
        for (int j = 0; j < 2; j++) {
            int b = bm + ty*4 + i, d = bn + tx*2 + j;
            if (d < KD_) P[(size_t)b * KD_ + d] = acc[i][j];
        }
}

// ---------------- Kernel 2: finalize -> A2 = [Ah|Ah|Al|0] ----------------
__global__ __launch_bounds__(256) void finalize_kernel(const float* __restrict__ bp)
{
    int id = blockIdx.x * 256 + threadIdx.x;          // over BS_*KD_
    int b = id / KD_, d = id - b * KD_;
    float v = 0.f;
    if (d < DTOT_) {
        #pragma unroll
        for (int s = 0; s < KSPLIT; s++)
            v += P_buf[((size_t)s * BS_ + b) * KD_ + d];
        v += bp[d];
        if (d == 0)       v *= INV_SQRT_N_;
        else if (d <= 64) v *= INV_SQRT_N_ * SQRT2_;
    }
    __nv_bfloat16 h = __float2bfloat16_rn(v);
    __nv_bfloat16 l = __float2bfloat16_rn(v - __bfloat162float(h));
    __nv_bfloat16* row = A2 + (size_t)b * KP2;
    row[d] = h; row[KD_ + d] = h; row[2*KD_ + d] = l;
    if (d < KP2 - 3*KD_) row[3*KD_ + d] = __float2bfloat16_rn(0.f);
}

// ---------------- Kernel 3: build B2 = [Bh|Bl|Bh|0] ----------------
__global__ void build_B2_kernel(const float* __restrict__ Ws)
{
    int n = blockIdx.x, d = threadIdx.x;              // NN_ blocks x KD_ threads
    float v;
    if (d == 0) v = 1.0f;
    else if (d < 65) {
        int j = (d + 1) >> 1;
        int m = (j * n) & (NN_ - 1);
        float t = (float)(2 * m) * (1.0f / (float)NN_);
        float s, c; sincospif(t, &s, &c);
        v = (d & 1) ? c : s;
    } else if (d < DTOT_) v = Ws[(size_t)n * 64 + (d - 65)];
    else v = 0.f;
    __nv_bfloat16 h = __float2bfloat16_rn(v);
    __nv_bfloat16 l = __float2bfloat16_rn(v - __bfloat162float(h));
    __nv_bfloat16* row = B2 + (size_t)n * KP2;
    row[d] = h; row[KD_ + d] = l; row[2*KD_ + d] = h;
    if (d < KP2 - 3*KD_) row[3*KD_ + d] = __float2bfloat16_rn(0.f);
}

// ---------------- Kernel 4: C = A2 @ B2^T via mma.sync bf16 ----------------
// BM=128, BN=128, BK=64 (128B rows, SW128 swizzle), 8 warps (2x4), warp 64x32
#define GM 128
#define GN 128
#define GK 64
#define NIT (KP2 / GK)          // 7
#define STG_A 16384             // bytes per A stage (128 rows x 128B)
#define SM_B0 32768             // B stages start

__global__ __launch_bounds__(256, 2) void gemm_kernel(float* __restrict__ C)
{
    extern __shared__ char sm[];
    const uint32_t sb = s2u(sm);
    const int tid = threadIdx.x, lane = tid & 31, wid = tid >> 5;
    const int wm = wid & 1, wn = wid >> 1;
    const int bm = blockIdx.y * GM, bn = blockIdx.x * GN;
    const char* gA = (const char*)(A2 + (size_t)bm * KP2);
    const char* gB = (const char*)(B2 + (size_t)bn * KP2);

    // loader mapping: 4 chunks/thread, row=id>>3 (0..127), c16=id&7
    const int lrow = tid >> 3;            // rows tid/8 .. +96 step 32
    const int lc = tid & 7;

    // ldmatrix per-lane address pieces
    const int arow = wm * 64 + (lane & 15);
    const uint32_t arx = (uint32_t)((arow & 7) << 4);
    const uint32_t acb = (uint32_t)((lane >> 4) * 16);
    const int brow = wn * 32 + (lane & 7) + ((lane >> 4) & 1) * 8;
    const uint32_t brx = (uint32_t)((brow & 7) << 4);
    const uint32_t bcb = (uint32_t)(((lane >> 3) & 1) * 16);

    float acc[4][4][4] = {};

    // prologue: load tile 0 into stage 0
    {
        #pragma unroll
        for (int t = 0; t < 4; t++) {
            int row = lrow + t * 32;
            uint32_t so = (uint32_t)(row * 128 + lc * 16);
            so ^= (so >> 3) & 0x70;
            CP_ASYNC16(sb + so,          gA + (size_t)row * (KP2*2) + lc * 16);
            CP_ASYNC16(sb + SM_B0 + so,  gB + (size_t)row * (KP2*2) + lc * 16);
        }
        CP_COMMIT();
    }

    for (int kt = 0; kt < NIT; kt++) {
        if (kt + 1 < NIT) {
            int s = (kt + 1) & 1;
            size_t koff = (size_t)(kt + 1) * GK * 2;
            #pragma unroll
            for (int t = 0; t < 4; t++) {
                int row = lrow + t * 32;
                uint32_t so = (uint32_t)(row * 128 + lc * 16);
                so ^= (so >> 3) & 0x70;
                CP_ASYNC16(sb + s * STG_A + so,         gA + (size_t)row * (KP2*2) + koff + lc * 16);
                CP_ASYNC16(sb + SM_B0 + s * STG_A + so, gB + (size_t)row * (KP2*2) + koff + lc * 16);
            }
            CP_COMMIT();
            CP_WAIT(1);
        } else {
            CP_WAIT(0);
        }
        __syncthreads();

        const int s = kt & 1;
        const uint32_t ab = sb + s * STG_A;
        const uint32_t bb = sb + SM_B0 + s * STG_A;
        #pragma unroll
        for (int ks = 0; ks < 4; ks++) {
            uint32_t af[4][4], bf[2][4];
            #pragma unroll
            for (int mi = 0; mi < 4; mi++)
                LDSM4(af[mi], ab + (uint32_t)((arow + mi * 16) * 128) + ((ks * 32 + acb) ^ arx));
            #pragma unroll
            for (int nb = 0; nb < 2; nb++)
                LDSM4(bf[nb], bb + (uint32_t)((brow + nb * 16) * 128) + ((ks * 32 + bcb) ^ brx));
            #pragma unroll
            for (int mi = 0; mi < 4; mi++) {
                #pragma unroll
                for (int ni = 0; ni < 4; ni++) {
                    uint32_t bpair[2] = { bf[ni >> 1][(ni & 1) * 2], bf[ni >> 1][(ni & 1) * 2 + 1] };
                    MMA16816(acc[mi][ni], af[mi], bpair);
                }
            }
        }
        __syncthreads();
    }

    // epilogue: direct float2 stores
    #pragma unroll
    for (int mi = 0; mi < 4; mi++) {
        int m0 = bm + wm * 64 + mi * 16 + (lane >> 2);
        #pragma unroll
        for (int ni = 0; ni < 4; ni++) {
            int n0 = bn + wn * 32 + ni * 8 + (lane & 3) * 2;
            *(float2*)(&C[(size_t)m0 * NN_ + n0])       = make_float2(acc[mi][ni][0], acc[mi][ni][1]);
            *(float2*)(&C[(size_t)(m0 + 8) * NN_ + n0]) = make_float2(acc[mi][ni][2], acc[mi][ni][3]);
        }
    }
}

// ---------------- launch ----------------
extern "C" void kernel_launch(void* const* d_in, const int* in_sizes, int n_in,
                              void* d_out, int out_size)
{
    const float* x  = (const float*)d_in[0];
    const float* Wp = (const float*)d_in[1];
    const float* bp = (const float*)d_in[2];
    const float* Ws = (const float*)d_in[3];
    float* out = (float*)d_out;

    static int smem_set = 0;
    if (!smem_set) {
        cudaFuncSetAttribute(gemm_kernel, cudaFuncAttributeMaxDynamicSharedMemorySize, 65536);
        smem_set = 1;
    }

    proj_kernel<<<dim3(5, BS_ / BM1, KSPLIT), 256>>>(x, Wp);
    finalize_kernel<<<(BS_ * KD_) / 256, 256>>>(bp);
    build_B2_kernel<<<NN_, KD_>>>(Ws);
    gemm_kernel<<<dim3(NN_ / GN, BS_ / GM), 256, 65536>>>(out);
}

// round 8
// speedup vs baseline: 2.9313x; 1.2277x over previous
#include <cuda_runtime.h>
#include <cuda_bf16.h>
#include <cstdint>

#define BS_     4096
#define IN_DIM_ 2048
#define NN_     16384
#define DTOT_   129
#define KD_     144          // logical K of big GEMM (129 padded to 144)
#define KP2     448          // tripled K (3*144) padded to 448
#define PK      2048         // proj inner dim
#define PN      192          // proj output dim padded (>=129)
#define PSPLIT  8
#define PCH     (PK / PSPLIT)   // 256
#define INV_SQRT_N_ 0.0078125f
#define SQRT2_      1.41421356237309515f

__device__ __nv_bfloat16 Xh[BS_ * PK], Xl[BS_ * PK];
__device__ __nv_bfloat16 Wh2[PN * PK], Wl2[PN * PK];
__device__ float         Pp[PSPLIT * BS_ * PN];
__device__ __nv_bfloat16 A2[BS_ * KP2];     // [b][k'] = [Ah | Ah | Al | 0]
__device__ __nv_bfloat16 B2[NN_ * KP2];     // [n][k'] = [Bh | Bl | Bh | 0]

// ---------------- PTX helpers ----------------
__device__ __forceinline__ uint32_t s2u(const void* p) {
    uint32_t a; asm("{.reg .u64 t; cvta.to.shared.u64 t,%1; cvt.u32.u64 %0,t;}" : "=r"(a) : "l"(p));
    return a;
}
#define CP_ASYNC16(dst, src) asm volatile("cp.async.cg.shared.global [%0], [%1], 16;" :: "r"(dst), "l"(src))
#define CP_COMMIT()          asm volatile("cp.async.commit_group;" ::: "memory")
#define CP_WAIT(n)           asm volatile("cp.async.wait_group %0;" :: "n"(n) : "memory")
#define LDSM4(r, addr) asm volatile("ldmatrix.sync.aligned.m8n8.x4.shared.b16 {%0,%1,%2,%3}, [%4];" \
    : "=r"((r)[0]), "=r"((r)[1]), "=r"((r)[2]), "=r"((r)[3]) : "r"(addr))
#define MMA16816(d, a, b) asm volatile( \
    "mma.sync.aligned.m16n8k16.row.col.f32.bf16.bf16.f32 " \
    "{%0,%1,%2,%3}, {%4,%5,%6,%7}, {%8,%9}, {%0,%1,%2,%3};" \
    : "+f"((d)[0]), "+f"((d)[1]), "+f"((d)[2]), "+f"((d)[3]) \
    : "r"((a)[0]), "r"((a)[1]), "r"((a)[2]), "r"((a)[3]), "r"((b)[0]), "r"((b)[1]))

union BF4 { __nv_bfloat16 b[4]; uint2 u; };

// ---------------- split x into bf16 hi/lo ----------------
__global__ __launch_bounds__(256) void split_x_kernel(const float* __restrict__ x)
{
    int id = blockIdx.x * 256 + threadIdx.x;           // over BS_*PK/4
    float4 v = ((const float4*)x)[id];
    float vv[4] = {v.x, v.y, v.z, v.w};
    BF4 h, l;
    #pragma unroll
    for (int i = 0; i < 4; i++) {
        h.b[i] = __float2bfloat16_rn(vv[i]);
        l.b[i] = __float2bfloat16_rn(vv[i] - __bfloat162float(h.b[i]));
    }
    ((uint2*)Xh)[id] = h.u;
    ((uint2*)Xl)[id] = l.u;
}

// ---------------- split W_proj into padded bf16 hi/lo [PN][PK] ----------------
__global__ __launch_bounds__(256) void split_w_kernel(const float* __restrict__ Wp)
{
    int id = blockIdx.x * 256 + threadIdx.x;           // over PN*PK/4
    int row = (id * 4) / PK;
    BF4 h, l;
    if (row < DTOT_) {
        float4 v = ((const float4*)Wp)[id - (size_t)0];   // same linear index: rows aligned
        // note: Wp has exactly PK cols, rows 0..DTOT_-1 ; id*4 < DTOT_*PK here
        float vv[4] = {v.x, v.y, v.z, v.w};
        #pragma unroll
        for (int i = 0; i < 4; i++) {
            h.b[i] = __float2bfloat16_rn(vv[i]);
            l.b[i] = __float2bfloat16_rn(vv[i] - __bfloat162float(h.b[i]));
        }
    } else {
        #pragma unroll
        for (int i = 0; i < 4; i++) { h.b[i] = __float2bfloat16_rn(0.f); l.b[i] = h.b[i]; }
    }
    ((uint2*)Wh2)[id] = h.u;
    ((uint2*)Wl2)[id] = l.u;
}

// ---------------- proj via tensor cores: Pp[s] += x_tile @ W^T ----------------
// BM=64, BN=192, BK=64; 8 warps (2m x 4n), warp tile 32x48; 12 k-tiles
#define QM 64
#define QSTG 32768      // per-stage bytes: A 8KB @ +0, B 24KB @ +8192

__global__ __launch_bounds__(256, 2) void proj_mma_kernel()
{
    extern __shared__ char sm[];
    const uint32_t sb = s2u(sm);
    const int tid = threadIdx.x, lane = tid & 31, wid = tid >> 5;
    const int wm = wid & 1, wn = wid >> 1;
    const int s = blockIdx.x;
    const int bm = blockIdx.y * QM;

    const int arow = wm * 32 + (lane & 15);
    const uint32_t arx = (uint32_t)((arow & 7) << 4);
    const uint32_t acb = (uint32_t)((lane >> 4) * 16);
    const int brow = wn * 48 + (lane & 7) + ((lane >> 4) & 1) * 8;
    const uint32_t brx = (uint32_t)((brow & 7) << 4);
    const uint32_t bcb = (uint32_t)(((lane >> 3) & 1) * 16);

    float acc[2][6][4] = {};

    auto load_tile = [&](int it, int stg) {
        int term = it >> 2;
        int k0 = s * PCH + (it & 3) * 64;
        const __nv_bfloat16* Ap = (term == 2) ? Xl : Xh;
        const __nv_bfloat16* Bp = (term == 1) ? Wl2 : Wh2;
        const char* gA = (const char*)(Ap + (size_t)bm * PK + k0);
        const char* gB = (const char*)(Bp + k0);
        uint32_t base = sb + stg * QSTG;
        #pragma unroll
        for (int t = 0; t < 2; t++) {
            int id = tid + t * 256, row = id >> 3, c = id & 7;
            uint32_t so = (uint32_t)(row * 128 + c * 16); so ^= (so >> 3) & 0x70;
            CP_ASYNC16(base + so, gA + (size_t)row * (PK * 2) + c * 16);
        }
        #pragma unroll
        for (int t = 0; t < 6; t++) {
            int id = tid + t * 256, row = id >> 3, c = id & 7;
            uint32_t so = (uint32_t)(row * 128 + c * 16); so ^= (so >> 3) & 0x70;
            CP_ASYNC16(base + 8192 + so, gB + (size_t)row * (PK * 2) + c * 16);
        }
        CP_COMMIT();
    };

    load_tile(0, 0);
    for (int it = 0; it < 12; it++) {
        if (it + 1 < 12) { load_tile(it + 1, (it + 1) & 1); CP_WAIT(1); }
        else CP_WAIT(0);
        __syncthreads();
        const uint32_t ab = sb + (it & 1) * QSTG;
        const uint32_t bb = ab + 8192;
        #pragma unroll
        for (int ks = 0; ks < 4; ks++) {
            uint32_t af[2][4], bf[3][4];
            #pragma unroll
            for (int mi = 0; mi < 2; mi++)
                LDSM4(af[mi], ab + (uint32_t)((arow + mi * 16) * 128) + ((ks * 32 + acb) ^ arx));
            #pragma unroll
            for (int nb = 0; nb < 3; nb++)
                LDSM4(bf[nb], bb + (uint32_t)((brow + nb * 16) * 128) + ((ks * 32 + bcb) ^ brx));
            #pragma unroll
            for (int mi = 0; mi < 2; mi++)
                #pragma unroll
                for (int ni = 0; ni < 6; ni++) {
                    uint32_t bp[2] = { bf[ni >> 1][(ni & 1) * 2], bf[ni >> 1][(ni & 1) * 2 + 1] };
                    MMA16816(acc[mi][ni], af[mi], bp);
                }
        }
        __syncthreads();
    }

    float* P = Pp + (size_t)s * BS_ * PN;
    #pragma unroll
    for (int mi = 0; mi < 2; mi++) {
        int m0 = bm + wm * 32 + mi * 16 + (lane >> 2);
        #pragma unroll
        for (int ni = 0; ni < 6; ni++) {
            int n0 = wn * 48 + ni * 8 + (lane & 3) * 2;
            *(float2*)(&P[(size_t)m0 * PN + n0])       = make_float2(acc[mi][ni][0], acc[mi][ni][1]);
            *(float2*)(&P[(size_t)(m0 + 8) * PN + n0]) = make_float2(acc[mi][ni][2], acc[mi][ni][3]);
        }
    }
}

// ---------------- finalize: sum partials + bias + scales -> A2 ----------------
__global__ __launch_bounds__(256) void finalize_kernel(const float* __restrict__ bp)
{
    int id = blockIdx.x * 256 + threadIdx.x;          // over BS_*KD_
    int b = id / KD_, d = id - b * KD_;
    float v = 0.f;
    if (d < DTOT_) {
        #pragma unroll
        for (int s = 0; s < PSPLIT; s++)
            v += Pp[((size_t)s * BS_ + b) * PN + d];
        v += bp[d];
        if (d == 0)       v *= INV_SQRT_N_;
        else if (d <= 64) v *= INV_SQRT_N_ * SQRT2_;
    }
    __nv_bfloat16 h = __float2bfloat16_rn(v);
    __nv_bfloat16 l = __float2bfloat16_rn(v - __bfloat162float(h));
    __nv_bfloat16* row = A2 + (size_t)b * KP2;
    row[d] = h; row[KD_ + d] = h; row[2*KD_ + d] = l;
    if (d < KP2 - 3*KD_) row[3*KD_ + d] = __float2bfloat16_rn(0.f);
}

// ---------------- build B2 = [Bh|Bl|Bh|0] ----------------
__global__ void build_B2_kernel(const float* __restrict__ Ws)
{
    int n = blockIdx.x, d = threadIdx.x;
    float v;
    if (d == 0) v = 1.0f;
    else if (d < 65) {
        int j = (d + 1) >> 1;
        int m = (j * n) & (NN_ - 1);
        float t = (float)(2 * m) * (1.0f / (float)NN_);
        float s, c; sincospif(t, &s, &c);
        v = (d & 1) ? c : s;
    } else if (d < DTOT_) v = Ws[(size_t)n * 64 + (d - 65)];
    else v = 0.f;
    __nv_bfloat16 h = __float2bfloat16_rn(v);
    __nv_bfloat16 l = __float2bfloat16_rn(v - __bfloat162float(h));
    __nv_bfloat16* row = B2 + (size_t)n * KP2;
    row[d] = h; row[KD_ + d] = l; row[2*KD_ + d] = h;
    if (d < KP2 - 3*KD_) row[3*KD_ + d] = __float2bfloat16_rn(0.f);
}

// ---------------- big GEMM: C = A2 @ B2^T, 3-stage cp.async + frag pipeline ----
#define GM 128
#define GN 128
#define GK 64
#define NIT (KP2 / GK)          // 7
#define STG 32768               // per stage: A 16KB @ +0, B 16KB @ +16384

__global__ __launch_bounds__(256, 2) void gemm_kernel(float* __restrict__ C)
{
    extern __shared__ char sm[];
    const uint32_t sb = s2u(sm);
    const int tid = threadIdx.x, lane = tid & 31, wid = tid >> 5;
    const int wm = wid & 1, wn = wid >> 1;
    const int bm = blockIdx.y * GM, bn = blockIdx.x * GN;
    const char* gA = (const char*)(A2 + (size_t)bm * KP2);
    const char* gB = (const char*)(B2 + (size_t)bn * KP2);

    const int lrow = tid >> 3;
    const int lc = tid & 7;

    const int arow = wm * 64 + (lane & 15);
    const uint32_t arx = (uint32_t)((arow & 7) << 4);
    const uint32_t acb = (uint32_t)((lane >> 4) * 16);
    const int brow = wn * 32 + (lane & 7) + ((lane >> 4) & 1) * 8;
    const uint32_t brx = (uint32_t)((brow & 7) << 4);
    const uint32_t bcb = (uint32_t)(((lane >> 3) & 1) * 16);

    float acc[4][4][4] = {};

    auto load_tile = [&](int kt, int stg) {
        size_t koff = (size_t)kt * GK * 2;
        uint32_t base = sb + stg * STG;
        #pragma unroll
        for (int t = 0; t < 4; t++) {
            int row = lrow + t * 32;
            uint32_t so = (uint32_t)(row * 128 + lc * 16); so ^= (so >> 3) & 0x70;
            CP_ASYNC16(base + so,         gA + (size_t)row * (KP2*2) + koff + lc * 16);
            CP_ASYNC16(base + 16384 + so, gB + (size_t)row * (KP2*2) + koff + lc * 16);
        }
        CP_COMMIT();
    };

    load_tile(0, 0);
    load_tile(1, 1);

    int st = 0;
    for (int kt = 0; kt < NIT; kt++) {
        if (kt + 2 < NIT) { load_tile(kt + 2, (kt + 2) % 3); CP_WAIT(2); }
        else if (kt + 1 < NIT) CP_WAIT(1);
        else CP_WAIT(0);
        __syncthreads();

        const uint32_t ab = sb + st * STG;
        const uint32_t bb = ab + 16384;

        uint32_t af[2][4][4], bf[2][2][4];
        #pragma unroll
        for (int mi = 0; mi < 4; mi++)
            LDSM4(af[0][mi], ab + (uint32_t)((arow + mi * 16) * 128) + ((0 + acb) ^ arx));
        #pragma unroll
        for (int nb = 0; nb < 2; nb++)
            LDSM4(bf[0][nb], bb + (uint32_t)((brow + nb * 16) * 128) + ((0 + bcb) ^ brx));

        #pragma unroll
        for (int ks = 0; ks < 4; ks++) {
            const int cur = ks & 1, nxt = cur ^ 1;
            if (ks < 3) {
                #pragma unroll
                for (int mi = 0; mi < 4; mi++)
                    LDSM4(af[nxt][mi], ab + (uint32_t)((arow + mi * 16) * 128) + (((ks + 1) * 32 + acb) ^ arx));
                #pragma unroll
                for (int nb = 0; nb < 2; nb++)
                    LDSM4(bf[nxt][nb], bb + (uint32_t)((brow + nb * 16) * 128) + (((ks + 1) * 32 + bcb) ^ brx));
            }
            #pragma unroll
            for (int mi = 0; mi < 4; mi++)
                #pragma unroll
                for (int ni = 0; ni < 4; ni++) {
                    uint32_t bp[2] = { bf[cur][ni >> 1][(ni & 1) * 2], bf[cur][ni >> 1][(ni & 1) * 2 + 1] };
                    MMA16816(acc[mi][ni], af[cur][mi], bp);
                }
        }
        __syncthreads();
        st = (st + 1 == 3) ? 0 : st + 1;
    }

    #pragma unroll
    for (int mi = 0; mi < 4; mi++) {
        int m0 = bm + wm * 64 + mi * 16 + (lane >> 2);
        #pragma unroll
        for (int ni = 0; ni < 4; ni++) {
            int n0 = bn + wn * 32 + ni * 8 + (lane & 3) * 2;
            *(float2*)(&C[(size_t)m0 * NN_ + n0])       = make_float2(acc[mi][ni][0], acc[mi][ni][1]);
            *(float2*)(&C[(size_t)(m0 + 8) * NN_ + n0]) = make_float2(acc[mi][ni][2], acc[mi][ni][3]);
        }
    }
}

// ---------------- launch ----------------
extern "C" void kernel_launch(void* const* d_in, const int* in_sizes, int n_in,
                              void* d_out, int out_size)
{
    const float* x  = (const float*)d_in[0];
    const float* Wp = (const float*)d_in[1];
    const float* bp = (const float*)d_in[2];
    const float* Ws = (const float*)d_in[3];
    float* out = (float*)d_out;

    cudaFuncSetAttribute(gemm_kernel,     cudaFuncAttributeMaxDynamicSharedMemorySize, 3 * STG);
    cudaFuncSetAttribute(proj_mma_kernel, cudaFuncAttributeMaxDynamicSharedMemorySize, 2 * QSTG);

    split_x_kernel<<<(BS_ * PK / 4) / 256, 256>>>(x);
    split_w_kernel<<<(PN * PK / 4) / 256, 256>>>(Wp);
    proj_mma_kernel<<<dim3(PSPLIT, BS_ / QM), 256, 2 * QSTG>>>();
    finalize_kernel<<<(BS_ * KD_) / 256, 256>>>(bp);
    build_B2_kernel<<<NN_, KD_>>>(Ws);
    gemm_kernel<<<dim3(NN_ / GN, BS_ / GM), 256, 3 * STG>>>(out);
}